// round 5
// baseline (speedup 1.0000x reference)
#include <cuda_runtime.h>
#include <cuda_bf16.h>
#include <math.h>
#include <stdint.h>

#define B_ROWS   8192
#define D_INF    2048
#define D_BOT    1024
#define C_CLS    1000
#define C_PAD    1024
#define SHARE    500
#define NEG_FILL (-1e9f)
#define INV_TEMP 20.0f
#define EPSN     1e-12f

// ===================== scratch (static device globals) =====================
__device__ __align__(1024) __nv_bfloat16 g_feat3 [3][(size_t)B_ROWS * D_INF];
__device__ __align__(1024) __nv_bfloat16 g_Wb3   [3][(size_t)D_BOT  * D_INF];
__device__ __align__(1024) __nv_bfloat16 g_feats3[3][(size_t)B_ROWS * D_BOT];
__device__ __align__(1024) __nv_bfloat16 g_W1s   [3][(size_t)C_PAD  * D_BOT];
__device__ __align__(1024) __nv_bfloat16 g_sm1s  [2][(size_t)B_ROWS * C_PAD];
__device__ __align__(1024) __nv_bfloat16 g_cTs   [2][(size_t)D_BOT  * C_PAD];
__device__ __align__(1024) __nv_bfloat16 g_faug2 [2][(size_t)B_ROWS * D_BOT];
__device__ __align__(1024) __nv_bfloat16 g_W2s   [2][(size_t)C_PAD  * D_BOT];

// ===================== helpers =====================
__device__ __forceinline__ uint32_t smem_u32(const void* p) {
    return (uint32_t)__cvta_generic_to_shared(p);
}
__device__ __forceinline__ void cp16(uint32_t sdst, const void* gsrc) {
    asm volatile("cp.async.cg.shared.global [%0], [%1], 16;" :: "r"(sdst), "l"(gsrc));
}
#define CP_COMMIT() asm volatile("cp.async.commit_group;" ::: "memory")
#define CP_WAIT1()  asm volatile("cp.async.wait_group 1;" ::: "memory")

#define LDSM_X4(r0, r1, r2, r3, addr) \
    asm volatile("ldmatrix.sync.aligned.m8n8.x4.shared.b16 {%0,%1,%2,%3}, [%4];" \
        : "=r"(r0), "=r"(r1), "=r"(r2), "=r"(r3) : "r"(addr))
#define LDSM_X2(r0, r1, addr) \
    asm volatile("ldmatrix.sync.aligned.m8n8.x2.shared.b16 {%0,%1}, [%2];" \
        : "=r"(r0), "=r"(r1) : "r"(addr))

__device__ __forceinline__ void mma_16816(float* c, const uint32_t* a, const uint32_t* b) {
    asm volatile(
        "mma.sync.aligned.m16n8k16.row.col.f32.bf16.bf16.f32 "
        "{%0,%1,%2,%3}, {%4,%5,%6,%7}, {%8,%9}, {%0,%1,%2,%3};"
        : "+f"(c[0]), "+f"(c[1]), "+f"(c[2]), "+f"(c[3])
        : "r"(a[0]), "r"(a[1]), "r"(a[2]), "r"(a[3]), "r"(b[0]), "r"(b[1]));
}

__device__ __forceinline__ void split2f(float x, __nv_bfloat16& h, __nv_bfloat16& m) {
    h = __float2bfloat16(x);
    m = __float2bfloat16(x - __bfloat162float(h));
}
__device__ __forceinline__ __nv_bfloat16 third_comp(float x, __nv_bfloat16 h, __nv_bfloat16 m) {
    return __float2bfloat16((x - __bfloat162float(h)) - __bfloat162float(m));
}

// ===================== bf16 split GEMM via mma.sync =====================
// C[8192, Nout](+epilogue) = sum_{ca+cb<NC} A_ca[8192,K] @ B_cb[1024,K]^T
// block tile 128x128, BK=32, 8 warps (warp tile 64x32), 3-stage cp.async ring.
//  MODE 0: +bias[n], store stride D_BOT, ALSO writes split3 of result to oc0..2
//  MODE 1: plain, store stride Nout, guard n<Nout
//  MODE 2: +aux[m*D_BOT+n], store stride D_BOT
//  MODE 3: *INV_TEMP, store stride Nout, guard
template <int NC, int MODE>
__global__ void __launch_bounds__(256)
gemm_mma(const __nv_bfloat16* __restrict__ A, size_t sA,
         const __nv_bfloat16* __restrict__ B, size_t sB,
         float* __restrict__ C, int K, int Nout,
         const float* __restrict__ aux,
         __nv_bfloat16* __restrict__ oc0,
         __nv_bfloat16* __restrict__ oc1,
         __nv_bfloat16* __restrict__ oc2)
{
    extern __shared__ __align__(128) char smem[];
    const uint32_t sb = smem_u32(smem);
    const int tid = threadIdx.x;
    const int wid = tid >> 5;
    const int lane = tid & 31;
    const int bm = blockIdx.y * 128;
    const int bn = blockIdx.x * 128;

    constexpr int TILEB = 128 * 80;            // 10240 B per operand tile (64B data + 16B pad rows)
    constexpr int STAGE = 2 * NC * TILEB;

    const int wm = (wid >> 2) * 64;
    const int wn = (wid & 3) * 32;

    const uint32_t a_lo = (uint32_t)((lane & 15) * 80 + (lane >> 4) * 16);
    const uint32_t b_lo = (uint32_t)((lane & 7) * 80 + ((lane >> 3) & 1) * 16);

    const int l_row0 = tid >> 2;
    const int l_seg = tid & 3;

    float acc[4][4][4];
#pragma unroll
    for (int i = 0; i < 4; i++)
#pragma unroll
        for (int j = 0; j < 4; j++)
#pragma unroll
            for (int q = 0; q < 4; q++) acc[i][j][q] = 0.f;

    const int nch = K >> 5;

    auto load_chunk = [&](int ci) {
        const int s = ci % 3;
        const int k0 = ci << 5;
        const uint32_t st = sb + (uint32_t)s * STAGE;
#pragma unroll
        for (int c = 0; c < 2 * NC; c++) {
            const __nv_bfloat16* base = (c < NC)
                ? A + (size_t)c * sA + (size_t)bm * K + k0
                : B + (size_t)(c - NC) * sB + (size_t)bn * K + k0;
#pragma unroll
            for (int j = 0; j < 2; j++) {
                const int row = l_row0 + j * 64;
                cp16(st + (uint32_t)(c * TILEB + row * 80 + l_seg * 16),
                     base + (size_t)row * K + l_seg * 8);
            }
        }
        CP_COMMIT();
    };

    load_chunk(0);
    load_chunk(1);

    for (int i = 0; i < nch; i++) {
        CP_WAIT1();
        __syncthreads();
        if (i + 2 < nch) load_chunk(i + 2);   // targets buf (i+2)%3 == (i-1)%3, protected by sync
        const uint32_t st = sb + (uint32_t)(i % 3) * STAGE;
#pragma unroll
        for (int kk = 0; kk < 2; kk++) {
            uint32_t bfr[NC][4][2];
#pragma unroll
            for (int c = 0; c < NC; c++)
#pragma unroll
                for (int nt = 0; nt < 4; nt++)
                    LDSM_X2(bfr[c][nt][0], bfr[c][nt][1],
                            st + (uint32_t)((NC + c) * TILEB) + (uint32_t)(wn * 80) + b_lo
                               + (uint32_t)(nt * 8 * 80 + kk * 32));
#pragma unroll
            for (int ca = 0; ca < NC; ca++) {
                uint32_t afr[4][4];
#pragma unroll
                for (int mt = 0; mt < 4; mt++)
                    LDSM_X4(afr[mt][0], afr[mt][1], afr[mt][2], afr[mt][3],
                            st + (uint32_t)(ca * TILEB) + (uint32_t)(wm * 80) + a_lo
                               + (uint32_t)(mt * 16 * 80 + kk * 32));
#pragma unroll
                for (int cb = 0; cb < NC; cb++) {
                    if (ca + cb < NC) {
#pragma unroll
                        for (int mt = 0; mt < 4; mt++)
#pragma unroll
                            for (int nt = 0; nt < 4; nt++)
                                mma_16816(acc[mt][nt], afr[mt], bfr[cb][nt]);
                    }
                }
            }
        }
    }

    // ---------------- epilogue ----------------
    const int r0 = lane >> 2;
    const int c0 = (lane & 3) * 2;
#pragma unroll
    for (int mt = 0; mt < 4; mt++) {
#pragma unroll
        for (int half = 0; half < 2; half++) {
            const int m = bm + wm + mt * 16 + r0 + half * 8;
#pragma unroll
            for (int nt = 0; nt < 4; nt++) {
                const int n = bn + wn + nt * 8 + c0;
                float v0 = acc[mt][nt][half * 2 + 0];
                float v1 = acc[mt][nt][half * 2 + 1];
                if (MODE == 0) {
                    const float2 bs = *reinterpret_cast<const float2*>(aux + n);
                    v0 += bs.x; v1 += bs.y;
                    const size_t o = (size_t)m * D_BOT + n;
                    *reinterpret_cast<float2*>(C + o) = make_float2(v0, v1);
                    __nv_bfloat16 h0, mm0, h1, mm1;
                    split2f(v0, h0, mm0); split2f(v1, h1, mm1);
                    __nv_bfloat162 ph; ph.x = h0; ph.y = h1;
                    __nv_bfloat162 pm; pm.x = mm0; pm.y = mm1;
                    __nv_bfloat162 pl;
                    pl.x = third_comp(v0, h0, mm0);
                    pl.y = third_comp(v1, h1, mm1);
                    *reinterpret_cast<__nv_bfloat162*>(oc0 + o) = ph;
                    *reinterpret_cast<__nv_bfloat162*>(oc1 + o) = pm;
                    *reinterpret_cast<__nv_bfloat162*>(oc2 + o) = pl;
                } else if (MODE == 2) {
                    const float2 r = *reinterpret_cast<const float2*>(aux + (size_t)m * D_BOT + n);
                    v0 += r.x; v1 += r.y;
                    *reinterpret_cast<float2*>(C + (size_t)m * D_BOT + n) = make_float2(v0, v1);
                } else {
                    if (MODE == 3) { v0 *= INV_TEMP; v1 *= INV_TEMP; }
                    if (n < Nout)
                        *reinterpret_cast<float2*>(C + (size_t)m * Nout + n) = make_float2(v0, v1);
                }
            }
        }
    }
}

// ===================== split kernels =====================
template <int NCOMP>
__global__ void split_pad(const float* __restrict__ src, int src_rows, int colshift,
                          __nv_bfloat16* __restrict__ c0, __nv_bfloat16* __restrict__ c1,
                          __nv_bfloat16* __restrict__ c2, int pad_rows)
{
    const size_t total2 = ((size_t)pad_rows << colshift) >> 1;
    for (size_t i = blockIdx.x * (size_t)blockDim.x + threadIdx.x; i < total2;
         i += (size_t)gridDim.x * blockDim.x) {
        const int row = (int)((i * 2) >> colshift);
        float2 v = (row < src_rows) ? reinterpret_cast<const float2*>(src)[i]
                                    : make_float2(0.f, 0.f);
        __nv_bfloat16 h0, m0, h1, m1;
        split2f(v.x, h0, m0); split2f(v.y, h1, m1);
        __nv_bfloat162 ph; ph.x = h0; ph.y = h1;
        __nv_bfloat162 pm; pm.x = m0; pm.y = m1;
        reinterpret_cast<__nv_bfloat162*>(c0)[i] = ph;
        reinterpret_cast<__nv_bfloat162*>(c1)[i] = pm;
        if (NCOMP == 3) {
            __nv_bfloat162 pl;
            pl.x = third_comp(v.x, h0, m0);
            pl.y = third_comp(v.y, h1, m1);
            reinterpret_cast<__nv_bfloat162*>(c2)[i] = pl;
        }
    }
}

// fused: per-row L2 norm of features_aug, then scaled split2 -> faug2
__global__ void __launch_bounds__(256)
norm_split2(const float* __restrict__ src,
            __nv_bfloat16* __restrict__ c0, __nv_bfloat16* __restrict__ c1)
{
    const int row = blockIdx.x;
    const int t = threadIdx.x;
    float4 v = reinterpret_cast<const float4*>(src + (size_t)row * D_BOT)[t];
    float s = v.x * v.x + v.y * v.y + v.z * v.z + v.w * v.w;
    __shared__ float sh[256];
    sh[t] = s;
    __syncthreads();
#pragma unroll
    for (int k = 128; k > 0; k >>= 1) {
        if (t < k) sh[t] += sh[t + k];
        __syncthreads();
    }
    const float inv = 1.f / fmaxf(sqrtf(sh[0]), EPSN);
    v.x *= inv; v.y *= inv; v.z *= inv; v.w *= inv;
    const float x[4] = {v.x, v.y, v.z, v.w};
    const size_t base2 = ((size_t)row * D_BOT + t * 4) >> 1;   // index in bf162 units
#pragma unroll
    for (int p = 0; p < 2; p++) {
        __nv_bfloat16 h0, m0, h1, m1;
        split2f(x[2 * p], h0, m0);
        split2f(x[2 * p + 1], h1, m1);
        __nv_bfloat162 ph; ph.x = h0; ph.y = h1;
        __nv_bfloat162 pm; pm.x = m0; pm.y = m1;
        reinterpret_cast<__nv_bfloat162*>(c0)[base2 + p] = ph;
        reinterpret_cast<__nv_bfloat162*>(c1)[base2 + p] = pm;
    }
}

__global__ void transpose_split2(const float* __restrict__ src)
{
    __shared__ float tile[32][33];
    const int bx = blockIdx.x * 32;  // d
    const int by = blockIdx.y * 32;  // c
    const int x = bx + threadIdx.x;
#pragma unroll
    for (int i = 0; i < 32; i += 8) {
        const int c = by + threadIdx.y + i;
        tile[threadIdx.y + i][threadIdx.x] = (c < C_CLS) ? src[(size_t)c * D_BOT + x] : 0.f;
    }
    __syncthreads();
    const int c2 = by + threadIdx.x;
#pragma unroll
    for (int i = 0; i < 32; i += 8) {
        const int d2 = bx + threadIdx.y + i;
        const float v = tile[threadIdx.x][threadIdx.y + i];
        __nv_bfloat16 h, m;
        split2f(v, h, m);
        const size_t o = (size_t)d2 * C_PAD + c2;
        g_cTs[0][o] = h;
        g_cTs[1][o] = m;
    }
}

// ===================== masked softmax -> sm1 split2 (col-padded) =====================
__global__ void __launch_bounds__(256)
mask_softmax(const float* __restrict__ logits)
{
    const int row = blockIdx.x;
    const float* x = logits + (size_t)row * C_CLS;
    const int t = threadIdx.x;

    float v[4];
    float lmax = -INFINITY;
    int limax = C_CLS;
#pragma unroll
    for (int i = 0; i < 4; i++) {
        const int j = t + i * 256;
        const float val = (j < C_CLS) ? x[j] : -INFINITY;
        v[i] = val;
        if (val > lmax) { lmax = val; limax = j; }
    }
    __shared__ float smax[256];
    __shared__ int   simax[256];
    smax[t] = lmax; simax[t] = limax;
    __syncthreads();
#pragma unroll
    for (int s = 128; s > 0; s >>= 1) {
        if (t < s) {
            const float o = smax[t + s]; const int oi = simax[t + s];
            if (o > smax[t] || (o == smax[t] && oi < simax[t])) { smax[t] = o; simax[t] = oi; }
        }
        __syncthreads();
    }
    const int predict = simax[0];
    const float rowmax = smax[0];
    const bool priv = (predict >= SHARE);

    float e[4];
    float lsum = 0.f;
#pragma unroll
    for (int i = 0; i < 4; i++) {
        const int j = t + i * 256;
        float ee = 0.f;
        if (j < C_CLS) {
            bool mask;
            if (j == predict) mask = false;
            else if (priv)    mask = true;
            else              mask = (j < SHARE);
            ee = expf((mask ? NEG_FILL : v[i]) - rowmax);
            lsum += ee;
        }
        e[i] = ee;
    }
    __shared__ float ssum[256];
    ssum[t] = lsum;
    __syncthreads();
#pragma unroll
    for (int s = 128; s > 0; s >>= 1) {
        if (t < s) ssum[t] += ssum[t + s];
        __syncthreads();
    }
    const float inv = 1.f / ssum[0];

    __nv_bfloat16* o0 = g_sm1s[0] + (size_t)row * C_PAD;
    __nv_bfloat16* o1 = g_sm1s[1] + (size_t)row * C_PAD;
#pragma unroll
    for (int i = 0; i < 4; i++) {
        const int j = t + i * 256;
        const float p = (j < C_CLS) ? e[i] * inv : 0.f;
        __nv_bfloat16 h, m;
        split2f(p, h, m);
        o0[j] = h;
        o1[j] = m;
    }
}

// ===================== plain row softmax =====================
__global__ void __launch_bounds__(256)
softmax_rows(const float* __restrict__ in, float* __restrict__ outp)
{
    const int row = blockIdx.x;
    const float* x = in + (size_t)row * C_CLS;
    const int t = threadIdx.x;
    float v[4];
    float lmax = -INFINITY;
#pragma unroll
    for (int i = 0; i < 4; i++) {
        const int j = t + i * 256;
        v[i] = (j < C_CLS) ? x[j] : -INFINITY;
        lmax = fmaxf(lmax, v[i]);
    }
    __shared__ float sh[256];
    sh[t] = lmax;
    __syncthreads();
#pragma unroll
    for (int s = 128; s > 0; s >>= 1) {
        if (t < s) sh[t] = fmaxf(sh[t], sh[t + s]);
        __syncthreads();
    }
    const float rowmax = sh[0];
    __syncthreads();
    float e[4];
    float lsum = 0.f;
#pragma unroll
    for (int i = 0; i < 4; i++) {
        const int j = t + i * 256;
        float ee = 0.f;
        if (j < C_CLS) { ee = expf(v[i] - rowmax); lsum += ee; }
        e[i] = ee;
    }
    sh[t] = lsum;
    __syncthreads();
#pragma unroll
    for (int s = 128; s > 0; s >>= 1) {
        if (t < s) sh[t] += sh[t + s];
        __syncthreads();
    }
    const float inv = 1.f / sh[0];
    float* o = outp + (size_t)row * C_CLS;
#pragma unroll
    for (int i = 0; i < 4; i++) {
        const int j = t + i * 256;
        if (j < C_CLS) o[j] = e[i] * inv;
    }
}

// =====================================================================
extern "C" void kernel_launch(void* const* d_in, const int* in_sizes, int n_in,
                              void* d_out, int out_size)
{
    const float* features = (const float*)d_in[0];
    const float* W_b      = (const float*)d_in[1];
    const float* b_b      = (const float*)d_in[2];
    const float* W1       = (const float*)d_in[3];
    const float* W2       = (const float*)d_in[4];
    const float* centroid = (const float*)d_in[5];

    float* out = (float*)d_out;
    float* feats        = out;
    float* features_aug = feats + (size_t)B_ROWS * D_BOT;
    float* outputs1     = features_aug + (size_t)B_ROWS * D_BOT;
    float* outputs2     = outputs1 + (size_t)B_ROWS * C_CLS;
    float* softmax_out  = outputs2 + (size_t)B_ROWS * C_CLS;

    __nv_bfloat16 *feat3, *Wb3, *feats3, *W1s, *sm1s, *cTs, *faug2, *W2s;
    cudaGetSymbolAddress((void**)&feat3,  g_feat3);
    cudaGetSymbolAddress((void**)&Wb3,    g_Wb3);
    cudaGetSymbolAddress((void**)&feats3, g_feats3);
    cudaGetSymbolAddress((void**)&W1s,    g_W1s);
    cudaGetSymbolAddress((void**)&sm1s,   g_sm1s);
    cudaGetSymbolAddress((void**)&cTs,    g_cTs);
    cudaGetSymbolAddress((void**)&faug2,  g_faug2);
    cudaGetSymbolAddress((void**)&W2s,    g_W2s);

    const size_t S_feat  = (size_t)B_ROWS * D_INF;
    const size_t S_Wb    = (size_t)D_BOT  * D_INF;
    const size_t S_feats = (size_t)B_ROWS * D_BOT;
    const size_t S_W1    = (size_t)C_PAD  * D_BOT;
    const size_t S_sm1   = (size_t)B_ROWS * C_PAD;
    const size_t S_cT    = (size_t)D_BOT  * C_PAD;

    constexpr int TILEB = 128 * 80;
    constexpr int SMEM3 = 3 * (2 * 3 * TILEB);   // 184320
    constexpr int SMEM2 = 3 * (2 * 2 * TILEB);   // 122880
    cudaFuncSetAttribute(gemm_mma<3, 0>, cudaFuncAttributeMaxDynamicSharedMemorySize, SMEM3);
    cudaFuncSetAttribute(gemm_mma<3, 1>, cudaFuncAttributeMaxDynamicSharedMemorySize, SMEM3);
    cudaFuncSetAttribute(gemm_mma<2, 2>, cudaFuncAttributeMaxDynamicSharedMemorySize, SMEM2);
    cudaFuncSetAttribute(gemm_mma<2, 3>, cudaFuncAttributeMaxDynamicSharedMemorySize, SMEM2);

    const dim3 blk(256);
    const dim3 grid8(8, 64);

    // splits for GEMM1
    split_pad<3><<<1024, blk>>>(features, B_ROWS, 11, feat3, feat3 + S_feat, feat3 + 2 * S_feat, B_ROWS);
    split_pad<3><<<512,  blk>>>(W_b, D_BOT, 11, Wb3, Wb3 + S_Wb, Wb3 + 2 * S_Wb, D_BOT);

    // GEMM1: feats = features @ W_b^T + b_b  (epilogue also emits feats3 splits)
    gemm_mma<3, 0><<<grid8, blk, SMEM3>>>(feat3, S_feat, Wb3, S_Wb, feats, D_INF, D_BOT, b_b,
                                          feats3, feats3 + S_feats, feats3 + 2 * S_feats);

    // W1 split
    split_pad<3><<<512, blk>>>(W1, C_CLS, 10, W1s, W1s + S_W1, W1s + 2 * S_W1, C_PAD);

    // GEMM2: outputs1 = feats @ W1^T
    gemm_mma<3, 1><<<grid8, blk, SMEM3>>>(feats3, S_feats, W1s, S_W1, outputs1, D_BOT, C_CLS,
                                          nullptr, nullptr, nullptr, nullptr);

    // centroid^T split2 + masked softmax
    transpose_split2<<<dim3(D_BOT / 32, C_PAD / 32), dim3(32, 8)>>>(centroid);
    mask_softmax<<<B_ROWS, blk>>>(outputs1);

    // GEMM3: features_aug = sm1 @ centroid + feats
    gemm_mma<2, 2><<<grid8, blk, SMEM2>>>(sm1s, S_sm1, cTs, S_cT, features_aug, C_PAD, D_BOT,
                                          feats, nullptr, nullptr, nullptr);

    // fused normalize + split2
    norm_split2<<<B_ROWS, blk>>>(features_aug, faug2, faug2 + S_feats);
    split_pad<2><<<512, blk>>>(W2, C_CLS, 10, W2s, W2s + S_W1, nullptr, C_PAD);

    // GEMM4: outputs2 = x @ W2^T / TEMP
    gemm_mma<2, 3><<<grid8, blk, SMEM2>>>(faug2, S_feats, W2s, S_W1, outputs2, D_BOT, C_CLS,
                                          nullptr, nullptr, nullptr, nullptr);

    softmax_rows<<<B_ROWS, blk>>>(outputs2, softmax_out);
}

// round 6
// speedup vs baseline: 1.4269x; 1.4269x over previous
#include <cuda_runtime.h>
#include <cuda_fp16.h>
#include <math.h>
#include <stdint.h>

#define B_ROWS   8192
#define D_INF    2048
#define D_BOT    1024
#define C_CLS    1000
#define C_PAD    1024
#define SHARE    500
#define NEG_FILL (-1e9f)
#define EPSN     1e-12f
#define SW       512.0f           // weight pre-scale (keeps fp16 m-components normal)
#define SA4      32.0f            // GEMM4 A pre-scale

// ===================== scratch (static device globals) =====================
__device__ __align__(1024) __half g_feat2 [2][(size_t)B_ROWS * D_INF];
__device__ __align__(1024) __half g_Wb2   [2][(size_t)D_BOT  * D_INF];
__device__ __align__(1024) __half g_feats2[2][(size_t)B_ROWS * D_BOT];
__device__ __align__(1024) __half g_W1s   [2][(size_t)C_PAD  * D_BOT];
__device__ __align__(1024) __half g_sm1s  [2][(size_t)B_ROWS * C_PAD];
__device__ __align__(1024) __half g_cTs   [2][(size_t)D_BOT  * C_PAD];
__device__ __align__(1024) __half g_faug2 [2][(size_t)B_ROWS * D_BOT];
__device__ __align__(1024) __half g_W2s   [2][(size_t)C_PAD  * D_BOT];

// ===================== helpers =====================
__device__ __forceinline__ uint32_t smem_u32(const void* p) {
    return (uint32_t)__cvta_generic_to_shared(p);
}
__device__ __forceinline__ void cp16(uint32_t sdst, const void* gsrc) {
    asm volatile("cp.async.cg.shared.global [%0], [%1], 16;" :: "r"(sdst), "l"(gsrc));
}
#define CP_COMMIT() asm volatile("cp.async.commit_group;" ::: "memory")
#define CP_WAIT1()  asm volatile("cp.async.wait_group 1;" ::: "memory")

#define LDSM_X4(r0, r1, r2, r3, addr) \
    asm volatile("ldmatrix.sync.aligned.m8n8.x4.shared.b16 {%0,%1,%2,%3}, [%4];" \
        : "=r"(r0), "=r"(r1), "=r"(r2), "=r"(r3) : "r"(addr))
#define LDSM_X2(r0, r1, addr) \
    asm volatile("ldmatrix.sync.aligned.m8n8.x2.shared.b16 {%0,%1}, [%2];" \
        : "=r"(r0), "=r"(r1) : "r"(addr))

__device__ __forceinline__ void mma_16816(float* c, const uint32_t* a, const uint32_t* b) {
    asm volatile(
        "mma.sync.aligned.m16n8k16.row.col.f32.f16.f16.f32 "
        "{%0,%1,%2,%3}, {%4,%5,%6,%7}, {%8,%9}, {%0,%1,%2,%3};"
        : "+f"(c[0]), "+f"(c[1]), "+f"(c[2]), "+f"(c[3])
        : "r"(a[0]), "r"(a[1]), "r"(a[2]), "r"(a[3]), "r"(b[0]), "r"(b[1]));
}

__device__ __forceinline__ void split2h(float x, __half& h, __half& m) {
    h = __float2half_rn(x);
    m = __float2half_rn(x - __half2float(h));
}

// ===================== fp16 split GEMM via mma.sync =====================
// C[8192, Nout](+epilogue) = escale * sum_terms A_c[8192,K] @ B_c[1024,K]^T
// NC = 2 components per operand. NTERMS = 4 (all pairs) or 3 (drop m*m).
// block tile 128x128, BK=32, 8 warps (warp tile 64x32), 2-stage cp.async, 2 CTA/SM.
//  MODE 0: v = escale*acc + bias[n]; store stride D_BOT; also split2 -> oc0/oc1
//  MODE 1: v = escale*acc;           store stride Nout, guard n<Nout
//  MODE 2: v = escale*acc + aux[m*D_BOT+n]; store stride D_BOT
//  MODE 3: v = escale*acc;           store stride Nout, guard
template <int NTERMS, int MODE>
__global__ void __launch_bounds__(256, 2)
gemm_mma(const __half* __restrict__ A, size_t sA,
         const __half* __restrict__ B, size_t sB,
         float* __restrict__ C, int K, int Nout, float escale,
         const float* __restrict__ aux,
         __half* __restrict__ oc0, __half* __restrict__ oc1)
{
    extern __shared__ __align__(128) char smem[];
    const uint32_t sb = smem_u32(smem);
    const int tid = threadIdx.x;
    const int wid = tid >> 5;
    const int lane = tid & 31;
    const int bm = blockIdx.y * 128;
    const int bn = blockIdx.x * 128;

    constexpr int TILEB = 128 * 80;            // 10240 B (64B data + 16B pad per row)
    constexpr int STAGE = 4 * TILEB;           // 2 A-tiles + 2 B-tiles

    const int wm = (wid >> 2) * 64;
    const int wn = (wid & 3) * 32;

    const uint32_t a_lo = (uint32_t)((lane & 15) * 80 + (lane >> 4) * 16);
    const uint32_t b_lo = (uint32_t)((lane & 7) * 80 + ((lane >> 3) & 1) * 16);

    const int l_row0 = tid >> 2;
    const int l_seg = tid & 3;

    float acc[4][4][4];
#pragma unroll
    for (int i = 0; i < 4; i++)
#pragma unroll
        for (int j = 0; j < 4; j++)
#pragma unroll
            for (int q = 0; q < 4; q++) acc[i][j][q] = 0.f;

    const int nch = K >> 5;

    auto load_chunk = [&](int ci) {
        const int s = ci & 1;
        const int k0 = ci << 5;
        const uint32_t st = sb + (uint32_t)s * STAGE;
#pragma unroll
        for (int c = 0; c < 4; c++) {
            const __half* base = (c < 2)
                ? A + (size_t)c * sA + (size_t)bm * K + k0
                : B + (size_t)(c - 2) * sB + (size_t)bn * K + k0;
#pragma unroll
            for (int j = 0; j < 2; j++) {
                const int row = l_row0 + j * 64;
                cp16(st + (uint32_t)(c * TILEB + row * 80 + l_seg * 16),
                     base + (size_t)row * K + l_seg * 8);
            }
        }
        CP_COMMIT();
    };

    load_chunk(0);
    load_chunk(1);

    for (int i = 0; i < nch; i++) {
        CP_WAIT1();
        __syncthreads();
        const uint32_t st = sb + (uint32_t)(i & 1) * STAGE;
#pragma unroll
        for (int kk = 0; kk < 2; kk++) {
            uint32_t bfr[2][4][2];
#pragma unroll
            for (int c = 0; c < 2; c++)
#pragma unroll
                for (int nt = 0; nt < 4; nt++)
                    LDSM_X2(bfr[c][nt][0], bfr[c][nt][1],
                            st + (uint32_t)((2 + c) * TILEB) + (uint32_t)(wn * 80) + b_lo
                               + (uint32_t)(nt * 8 * 80 + kk * 32));
#pragma unroll
            for (int ca = 0; ca < 2; ca++) {
                uint32_t afr[4][4];
#pragma unroll
                for (int mt = 0; mt < 4; mt++)
                    LDSM_X4(afr[mt][0], afr[mt][1], afr[mt][2], afr[mt][3],
                            st + (uint32_t)(ca * TILEB) + (uint32_t)(wm * 80) + a_lo
                               + (uint32_t)(mt * 16 * 80 + kk * 32));
#pragma unroll
                for (int cb = 0; cb < 2; cb++) {
                    if (NTERMS == 4 || ca + cb < 2) {
#pragma unroll
                        for (int mt = 0; mt < 4; mt++)
#pragma unroll
                            for (int nt = 0; nt < 4; nt++)
                                mma_16816(acc[mt][nt], afr[mt], bfr[cb][nt]);
                    }
                }
            }
        }
        __syncthreads();
        if (i + 2 < nch) load_chunk(i + 2);
    }

    // ---------------- epilogue ----------------
    const int r0 = lane >> 2;
    const int c0 = (lane & 3) * 2;
#pragma unroll
    for (int mt = 0; mt < 4; mt++) {
#pragma unroll
        for (int half = 0; half < 2; half++) {
            const int m = bm + wm + mt * 16 + r0 + half * 8;
#pragma unroll
            for (int nt = 0; nt < 4; nt++) {
                const int n = bn + wn + nt * 8 + c0;
                float v0 = acc[mt][nt][half * 2 + 0] * escale;
                float v1 = acc[mt][nt][half * 2 + 1] * escale;
                if (MODE == 0) {
                    const float2 bs = *reinterpret_cast<const float2*>(aux + n);
                    v0 += bs.x; v1 += bs.y;
                    const size_t o = (size_t)m * D_BOT + n;
                    *reinterpret_cast<float2*>(C + o) = make_float2(v0, v1);
                    __half h0, mm0, h1, mm1;
                    split2h(v0, h0, mm0); split2h(v1, h1, mm1);
                    __half2 ph; ph.x = h0; ph.y = h1;
                    __half2 pm; pm.x = mm0; pm.y = mm1;
                    *reinterpret_cast<__half2*>(oc0 + o) = ph;
                    *reinterpret_cast<__half2*>(oc1 + o) = pm;
                } else if (MODE == 2) {
                    const float2 r = *reinterpret_cast<const float2*>(aux + (size_t)m * D_BOT + n);
                    v0 += r.x; v1 += r.y;
                    *reinterpret_cast<float2*>(C + (size_t)m * D_BOT + n) = make_float2(v0, v1);
                } else {
                    if (n < Nout)
                        *reinterpret_cast<float2*>(C + (size_t)m * Nout + n) = make_float2(v0, v1);
                }
            }
        }
    }
}

// ===================== split kernels =====================
__global__ void split2_scale(const float* __restrict__ src, int src_rows, int colshift,
                             float scale,
                             __half* __restrict__ c0, __half* __restrict__ c1, int pad_rows)
{
    const size_t total2 = ((size_t)pad_rows << colshift) >> 1;
    for (size_t i = blockIdx.x * (size_t)blockDim.x + threadIdx.x; i < total2;
         i += (size_t)gridDim.x * blockDim.x) {
        const int row = (int)((i * 2) >> colshift);
        float2 v = (row < src_rows) ? reinterpret_cast<const float2*>(src)[i]
                                    : make_float2(0.f, 0.f);
        v.x *= scale; v.y *= scale;
        __half h0, m0, h1, m1;
        split2h(v.x, h0, m0); split2h(v.y, h1, m1);
        __half2 ph; ph.x = h0; ph.y = h1;
        __half2 pm; pm.x = m0; pm.y = m1;
        reinterpret_cast<__half2*>(c0)[i] = ph;
        reinterpret_cast<__half2*>(c1)[i] = pm;
    }
}

// fused: per-row L2 norm of features_aug, scaled split2 (x * SA4 / ||row||) -> faug2
__global__ void __launch_bounds__(256)
norm_split2(const float* __restrict__ src,
            __half* __restrict__ c0, __half* __restrict__ c1)
{
    const int row = blockIdx.x;
    const int t = threadIdx.x;
    float4 v = reinterpret_cast<const float4*>(src + (size_t)row * D_BOT)[t];
    float s = v.x * v.x + v.y * v.y + v.z * v.z + v.w * v.w;
    __shared__ float sh[256];
    sh[t] = s;
    __syncthreads();
#pragma unroll
    for (int k = 128; k > 0; k >>= 1) {
        if (t < k) sh[t] += sh[t + k];
        __syncthreads();
    }
    const float inv = SA4 / fmaxf(sqrtf(sh[0]), EPSN);
    v.x *= inv; v.y *= inv; v.z *= inv; v.w *= inv;
    const float x[4] = {v.x, v.y, v.z, v.w};
    const size_t base2 = ((size_t)row * D_BOT + t * 4) >> 1;
#pragma unroll
    for (int p = 0; p < 2; p++) {
        __half h0, m0, h1, m1;
        split2h(x[2 * p], h0, m0);
        split2h(x[2 * p + 1], h1, m1);
        __half2 ph; ph.x = h0; ph.y = h1;
        __half2 pm; pm.x = m0; pm.y = m1;
        reinterpret_cast<__half2*>(c0)[base2 + p] = ph;
        reinterpret_cast<__half2*>(c1)[base2 + p] = pm;
    }
}

// centroid [C,D_BOT] -> cT*SW split2, [D_BOT rows, C_PAD cols]
__global__ void transpose_split2(const float* __restrict__ src)
{
    __shared__ float tile[32][33];
    const int bx = blockIdx.x * 32;  // d
    const int by = blockIdx.y * 32;  // c
    const int x = bx + threadIdx.x;
#pragma unroll
    for (int i = 0; i < 32; i += 8) {
        const int c = by + threadIdx.y + i;
        tile[threadIdx.y + i][threadIdx.x] = (c < C_CLS) ? src[(size_t)c * D_BOT + x] * SW : 0.f;
    }
    __syncthreads();
    const int c2 = by + threadIdx.x;
#pragma unroll
    for (int i = 0; i < 32; i += 8) {
        const int d2 = bx + threadIdx.y + i;
        const float v = tile[threadIdx.x][threadIdx.y + i];
        __half h, m;
        split2h(v, h, m);
        const size_t o = (size_t)d2 * C_PAD + c2;
        g_cTs[0][o] = h;
        g_cTs[1][o] = m;
    }
}

// ===================== masked softmax -> sm1 split2 (col-padded, fp16) ==============
__global__ void __launch_bounds__(256)
mask_softmax(const float* __restrict__ logits)
{
    const int row = blockIdx.x;
    const float* x = logits + (size_t)row * C_CLS;
    const int t = threadIdx.x;

    float v[4];
    float lmax = -INFINITY;
    int limax = C_CLS;
#pragma unroll
    for (int i = 0; i < 4; i++) {
        const int j = t + i * 256;
        const float val = (j < C_CLS) ? x[j] : -INFINITY;
        v[i] = val;
        if (val > lmax) { lmax = val; limax = j; }
    }
    __shared__ float smax[256];
    __shared__ int   simax[256];
    smax[t] = lmax; simax[t] = limax;
    __syncthreads();
#pragma unroll
    for (int s = 128; s > 0; s >>= 1) {
        if (t < s) {
            const float o = smax[t + s]; const int oi = simax[t + s];
            if (o > smax[t] || (o == smax[t] && oi < simax[t])) { smax[t] = o; simax[t] = oi; }
        }
        __syncthreads();
    }
    const int predict = simax[0];
    const float rowmax = smax[0];
    const bool priv = (predict >= SHARE);

    float e[4];
    float lsum = 0.f;
#pragma unroll
    for (int i = 0; i < 4; i++) {
        const int j = t + i * 256;
        float ee = 0.f;
        if (j < C_CLS) {
            bool mask;
            if (j == predict) mask = false;
            else if (priv)    mask = true;
            else              mask = (j < SHARE);
            ee = expf((mask ? NEG_FILL : v[i]) - rowmax);
            lsum += ee;
        }
        e[i] = ee;
    }
    __shared__ float ssum[256];
    ssum[t] = lsum;
    __syncthreads();
#pragma unroll
    for (int s = 128; s > 0; s >>= 1) {
        if (t < s) ssum[t] += ssum[t + s];
        __syncthreads();
    }
    const float inv = 1.f / ssum[0];

    __half* o0 = g_sm1s[0] + (size_t)row * C_PAD;
    __half* o1 = g_sm1s[1] + (size_t)row * C_PAD;
#pragma unroll
    for (int i = 0; i < 4; i++) {
        const int j = t + i * 256;
        const float p = (j < C_CLS) ? e[i] * inv : 0.f;
        __half h, m;
        split2h(p, h, m);
        o0[j] = h;
        o1[j] = m;
    }
}

// ===================== plain row softmax =====================
__global__ void __launch_bounds__(256)
softmax_rows(const float* __restrict__ in, float* __restrict__ outp)
{
    const int row = blockIdx.x;
    const float* x = in + (size_t)row * C_CLS;
    const int t = threadIdx.x;
    float v[4];
    float lmax = -INFINITY;
#pragma unroll
    for (int i = 0; i < 4; i++) {
        const int j = t + i * 256;
        v[i] = (j < C_CLS) ? x[j] : -INFINITY;
        lmax = fmaxf(lmax, v[i]);
    }
    __shared__ float sh[256];
    sh[t] = lmax;
    __syncthreads();
#pragma unroll
    for (int s = 128; s > 0; s >>= 1) {
        if (t < s) sh[t] = fmaxf(sh[t], sh[t + s]);
        __syncthreads();
    }
    const float rowmax = sh[0];
    __syncthreads();
    float e[4];
    float lsum = 0.f;
#pragma unroll
    for (int i = 0; i < 4; i++) {
        const int j = t + i * 256;
        float ee = 0.f;
        if (j < C_CLS) { ee = expf(v[i] - rowmax); lsum += ee; }
        e[i] = ee;
    }
    sh[t] = lsum;
    __syncthreads();
#pragma unroll
    for (int s = 128; s > 0; s >>= 1) {
        if (t < s) sh[t] += sh[t + s];
        __syncthreads();
    }
    const float inv = 1.f / sh[0];
    float* o = outp + (size_t)row * C_CLS;
#pragma unroll
    for (int i = 0; i < 4; i++) {
        const int j = t + i * 256;
        if (j < C_CLS) o[j] = e[i] * inv;
    }
}

// =====================================================================
extern "C" void kernel_launch(void* const* d_in, const int* in_sizes, int n_in,
                              void* d_out, int out_size)
{
    const float* features = (const float*)d_in[0];
    const float* W_b      = (const float*)d_in[1];
    const float* b_b      = (const float*)d_in[2];
    const float* W1       = (const float*)d_in[3];
    const float* W2       = (const float*)d_in[4];
    const float* centroid = (const float*)d_in[5];

    float* out = (float*)d_out;
    float* feats        = out;
    float* features_aug = feats + (size_t)B_ROWS * D_BOT;
    float* outputs1     = features_aug + (size_t)B_ROWS * D_BOT;
    float* outputs2     = outputs1 + (size_t)B_ROWS * C_CLS;
    float* softmax_out  = outputs2 + (size_t)B_ROWS * C_CLS;

    __half *feat2, *Wb2, *feats2, *W1s, *sm1s, *cTs, *faug2, *W2s;
    cudaGetSymbolAddress((void**)&feat2,  g_feat2);
    cudaGetSymbolAddress((void**)&Wb2,    g_Wb2);
    cudaGetSymbolAddress((void**)&feats2, g_feats2);
    cudaGetSymbolAddress((void**)&W1s,    g_W1s);
    cudaGetSymbolAddress((void**)&sm1s,   g_sm1s);
    cudaGetSymbolAddress((void**)&cTs,    g_cTs);
    cudaGetSymbolAddress((void**)&faug2,  g_faug2);
    cudaGetSymbolAddress((void**)&W2s,    g_W2s);

    const size_t S_feat  = (size_t)B_ROWS * D_INF;
    const size_t S_Wb    = (size_t)D_BOT  * D_INF;
    const size_t S_feats = (size_t)B_ROWS * D_BOT;
    const size_t S_W1    = (size_t)C_PAD  * D_BOT;
    const size_t S_sm1   = (size_t)B_ROWS * C_PAD;
    const size_t S_cT    = (size_t)D_BOT  * C_PAD;

    constexpr int TILEB = 128 * 80;
    constexpr int SMEMG = 2 * 4 * TILEB;   // 81920 — 2 CTAs/SM
    cudaFuncSetAttribute(gemm_mma<4, 0>, cudaFuncAttributeMaxDynamicSharedMemorySize, SMEMG);
    cudaFuncSetAttribute(gemm_mma<4, 1>, cudaFuncAttributeMaxDynamicSharedMemorySize, SMEMG);
    cudaFuncSetAttribute(gemm_mma<3, 2>, cudaFuncAttributeMaxDynamicSharedMemorySize, SMEMG);
    cudaFuncSetAttribute(gemm_mma<3, 3>, cudaFuncAttributeMaxDynamicSharedMemorySize, SMEMG);

    const dim3 blk(256);
    const dim3 grid8(8, 64);
    const float invSW = 1.0f / SW;

    // splits for GEMM1
    split2_scale<<<1024, blk>>>(features, B_ROWS, 11, 1.0f, feat2, feat2 + S_feat, B_ROWS);
    split2_scale<<<512,  blk>>>(W_b, D_BOT, 11, SW, Wb2, Wb2 + S_Wb, D_BOT);

    // GEMM1: feats = features @ W_b^T + b_b (epilogue emits feats2 split)
    gemm_mma<4, 0><<<grid8, blk, SMEMG>>>(feat2, S_feat, Wb2, S_Wb, feats, D_INF, D_BOT,
                                          invSW, b_b, feats2, feats2 + S_feats);

    // W1 split
    split2_scale<<<512, blk>>>(W1, C_CLS, 10, SW, W1s, W1s + S_W1, C_PAD);

    // GEMM2: outputs1 = feats @ W1^T
    gemm_mma<4, 1><<<grid8, blk, SMEMG>>>(feats2, S_feats, W1s, S_W1, outputs1, D_BOT, C_CLS,
                                          invSW, nullptr, nullptr, nullptr);

    // centroid^T split + masked softmax
    transpose_split2<<<dim3(D_BOT / 32, C_PAD / 32), dim3(32, 8)>>>(centroid);
    mask_softmax<<<B_ROWS, blk>>>(outputs1);

    // GEMM3: features_aug = sm1 @ centroid + feats
    gemm_mma<3, 2><<<grid8, blk, SMEMG>>>(sm1s, S_sm1, cTs, S_cT, features_aug, C_PAD, D_BOT,
                                          invSW, feats, nullptr, nullptr);

    // fused normalize (+*SA4) + split2
    norm_split2<<<B_ROWS, blk>>>(features_aug, faug2, faug2 + S_feats);
    split2_scale<<<512, blk>>>(W2, C_CLS, 10, SW, W2s, W2s + S_W1, C_PAD);

    // GEMM4: outputs2 = x @ W2^T / TEMP   (escale = 20 / (SW*SA4))
    gemm_mma<3, 3><<<grid8, blk, SMEMG>>>(faug2, S_feats, W2s, S_W1, outputs2, D_BOT, C_CLS,
                                          20.0f / (SW * SA4), nullptr, nullptr, nullptr);

    softmax_rows<<<B_ROWS, blk>>>(outputs2, softmax_out);
}

// round 7
// speedup vs baseline: 1.4321x; 1.0037x over previous
#include <cuda_runtime.h>
#include <cuda_fp16.h>
#include <math.h>
#include <stdint.h>

#define B_ROWS   8192
#define D_INF    2048
#define D_BOT    1024
#define C_CLS    1000
#define C_PAD    1024
#define SHARE    500
#define NEG_FILL (-1e9f)
#define EPSN     1e-12f
#define SW       512.0f           // weight pre-scale (keeps fp16 m-components normal)
#define SA4      32.0f            // GEMM4 A pre-scale

// ===================== scratch (static device globals) =====================
__device__ __align__(1024) __half g_feat2 [2][(size_t)B_ROWS * D_INF];
__device__ __align__(1024) __half g_Wb2   [2][(size_t)D_BOT  * D_INF];
__device__ __align__(1024) __half g_feats2[2][(size_t)B_ROWS * D_BOT];
__device__ __align__(1024) __half g_W1s   [2][(size_t)C_PAD  * D_BOT];
__device__ __align__(1024) __half g_sm1s  [2][(size_t)B_ROWS * C_PAD];
__device__ __align__(1024) __half g_cTs   [2][(size_t)D_BOT  * C_PAD];
__device__ __align__(1024) __half g_faug2 [2][(size_t)B_ROWS * D_BOT];
__device__ __align__(1024) __half g_W2s   [2][(size_t)C_PAD  * D_BOT];

// ===================== helpers =====================
__device__ __forceinline__ uint32_t smem_u32(const void* p) {
    return (uint32_t)__cvta_generic_to_shared(p);
}
__device__ __forceinline__ void cp16(uint32_t sdst, const void* gsrc) {
    asm volatile("cp.async.cg.shared.global [%0], [%1], 16;" :: "r"(sdst), "l"(gsrc));
}
#define CP_COMMIT() asm volatile("cp.async.commit_group;" ::: "memory")
#define CP_WAIT1()  asm volatile("cp.async.wait_group 1;" ::: "memory")

#define LDSM_X4(r0, r1, r2, r3, addr) \
    asm volatile("ldmatrix.sync.aligned.m8n8.x4.shared.b16 {%0,%1,%2,%3}, [%4];" \
        : "=r"(r0), "=r"(r1), "=r"(r2), "=r"(r3) : "r"(addr))
#define LDSM_X2(r0, r1, addr) \
    asm volatile("ldmatrix.sync.aligned.m8n8.x2.shared.b16 {%0,%1}, [%2];" \
        : "=r"(r0), "=r"(r1) : "r"(addr))

__device__ __forceinline__ void mma_16816(float* c, const uint32_t* a, const uint32_t* b) {
    asm volatile(
        "mma.sync.aligned.m16n8k16.row.col.f32.f16.f16.f32 "
        "{%0,%1,%2,%3}, {%4,%5,%6,%7}, {%8,%9}, {%0,%1,%2,%3};"
        : "+f"(c[0]), "+f"(c[1]), "+f"(c[2]), "+f"(c[3])
        : "r"(a[0]), "r"(a[1]), "r"(a[2]), "r"(a[3]), "r"(b[0]), "r"(b[1]));
}

__device__ __forceinline__ void split2h(float x, __half& h, __half& m) {
    h = __float2half_rn(x);
    m = __float2half_rn(x - __half2float(h));
}

// ===================== fp16 split GEMM via mma.sync =====================
// C[8192, Nout](+epilogue) = escale * sum_terms A_c[8192,K] @ B_c[1024,K]^T
// NC = 2 components per operand. NTERMS = 4 (all pairs) or 3 (drop m*m).
// block tile 128x128, BK=32, 8 warps (warp tile 64x32), 2-stage cp.async, 2 CTA/SM.
//  MODE 0: v = escale*acc + bias[n]; store stride D_BOT; also split2 -> oc0/oc1
//  MODE 1: v = escale*acc;           store stride Nout, guard n<Nout
//  MODE 2: v = escale*acc + aux[m*D_BOT+n]; store stride D_BOT
//  MODE 3: v = escale*acc;           store stride Nout, guard
template <int NTERMS, int MODE>
__global__ void __launch_bounds__(256, 2)
gemm_mma(const __half* __restrict__ A, size_t sA,
         const __half* __restrict__ B, size_t sB,
         float* __restrict__ C, int K, int Nout, float escale,
         const float* __restrict__ aux,
         __half* __restrict__ oc0, __half* __restrict__ oc1)
{
    extern __shared__ __align__(128) char smem[];
    const uint32_t sb = smem_u32(smem);
    const int tid = threadIdx.x;
    const int wid = tid >> 5;
    const int lane = tid & 31;
    const int bm = blockIdx.y * 128;
    const int bn = blockIdx.x * 128;

    constexpr int TILEB = 128 * 80;            // 10240 B (64B data + 16B pad per row)
    constexpr int STAGE = 4 * TILEB;           // 2 A-tiles + 2 B-tiles

    const int wm = (wid >> 2) * 64;
    const int wn = (wid & 3) * 32;

    const uint32_t a_lo = (uint32_t)((lane & 15) * 80 + (lane >> 4) * 16);
    const uint32_t b_lo = (uint32_t)((lane & 7) * 80 + ((lane >> 3) & 1) * 16);

    const int l_row0 = tid >> 2;
    const int l_seg = tid & 3;

    float acc[4][4][4];
#pragma unroll
    for (int i = 0; i < 4; i++)
#pragma unroll
        for (int j = 0; j < 4; j++)
#pragma unroll
            for (int q = 0; q < 4; q++) acc[i][j][q] = 0.f;

    const int nch = K >> 5;

    auto load_chunk = [&](int ci) {
        const int s = ci & 1;
        const int k0 = ci << 5;
        const uint32_t st = sb + (uint32_t)s * STAGE;
#pragma unroll
        for (int c = 0; c < 4; c++) {
            const __half* base = (c < 2)
                ? A + (size_t)c * sA + (size_t)bm * K + k0
                : B + (size_t)(c - 2) * sB + (size_t)bn * K + k0;
#pragma unroll
            for (int j = 0; j < 2; j++) {
                const int row = l_row0 + j * 64;
                cp16(st + (uint32_t)(c * TILEB + row * 80 + l_seg * 16),
                     base + (size_t)row * K + l_seg * 8);
            }
        }
        CP_COMMIT();
    };

    load_chunk(0);
    load_chunk(1);

    for (int i = 0; i < nch; i++) {
        CP_WAIT1();
        __syncthreads();
        const uint32_t st = sb + (uint32_t)(i & 1) * STAGE;
#pragma unroll
        for (int kk = 0; kk < 2; kk++) {
            uint32_t bfr[2][4][2];
#pragma unroll
            for (int c = 0; c < 2; c++)
#pragma unroll
                for (int nt = 0; nt < 4; nt++)
                    LDSM_X2(bfr[c][nt][0], bfr[c][nt][1],
                            st + (uint32_t)((2 + c) * TILEB) + (uint32_t)(wn * 80) + b_lo
                               + (uint32_t)(nt * 8 * 80 + kk * 32));
#pragma unroll
            for (int ca = 0; ca < 2; ca++) {
                uint32_t afr[4][4];
#pragma unroll
                for (int mt = 0; mt < 4; mt++)
                    LDSM_X4(afr[mt][0], afr[mt][1], afr[mt][2], afr[mt][3],
                            st + (uint32_t)(ca * TILEB) + (uint32_t)(wm * 80) + a_lo
                               + (uint32_t)(mt * 16 * 80 + kk * 32));
#pragma unroll
                for (int cb = 0; cb < 2; cb++) {
                    if (NTERMS == 4 || ca + cb < 2) {
#pragma unroll
                        for (int mt = 0; mt < 4; mt++)
#pragma unroll
                            for (int nt = 0; nt < 4; nt++)
                                mma_16816(acc[mt][nt], afr[mt], bfr[cb][nt]);
                    }
                }
            }
        }
        __syncthreads();
        if (i + 2 < nch) load_chunk(i + 2);
    }

    // ---------------- epilogue ----------------
    const int r0 = lane >> 2;
    const int c0 = (lane & 3) * 2;
#pragma unroll
    for (int mt = 0; mt < 4; mt++) {
#pragma unroll
        for (int half = 0; half < 2; half++) {
            const int m = bm + wm + mt * 16 + r0 + half * 8;
#pragma unroll
            for (int nt = 0; nt < 4; nt++) {
                const int n = bn + wn + nt * 8 + c0;
                float v0 = acc[mt][nt][half * 2 + 0] * escale;
                float v1 = acc[mt][nt][half * 2 + 1] * escale;
                if (MODE == 0) {
                    const float2 bs = *reinterpret_cast<const float2*>(aux + n);
                    v0 += bs.x; v1 += bs.y;
                    const size_t o = (size_t)m * D_BOT + n;
                    *reinterpret_cast<float2*>(C + o) = make_float2(v0, v1);
                    __half h0, mm0, h1, mm1;
                    split2h(v0, h0, mm0); split2h(v1, h1, mm1);
                    __half2 ph; ph.x = h0; ph.y = h1;
                    __half2 pm; pm.x = mm0; pm.y = mm1;
                    *reinterpret_cast<__half2*>(oc0 + o) = ph;
                    *reinterpret_cast<__half2*>(oc1 + o) = pm;
                } else if (MODE == 2) {
                    const float2 r = *reinterpret_cast<const float2*>(aux + (size_t)m * D_BOT + n);
                    v0 += r.x; v1 += r.y;
                    *reinterpret_cast<float2*>(C + (size_t)m * D_BOT + n) = make_float2(v0, v1);
                } else {
                    if (n < Nout)
                        *reinterpret_cast<float2*>(C + (size_t)m * Nout + n) = make_float2(v0, v1);
                }
            }
        }
    }
}

// ===================== split kernels =====================
__global__ void split2_scale(const float* __restrict__ src, int src_rows, int colshift,
                             float scale,
                             __half* __restrict__ c0, __half* __restrict__ c1, int pad_rows)
{
    const size_t total2 = ((size_t)pad_rows << colshift) >> 1;
    for (size_t i = blockIdx.x * (size_t)blockDim.x + threadIdx.x; i < total2;
         i += (size_t)gridDim.x * blockDim.x) {
        const int row = (int)((i * 2) >> colshift);
        float2 v = (row < src_rows) ? reinterpret_cast<const float2*>(src)[i]
                                    : make_float2(0.f, 0.f);
        v.x *= scale; v.y *= scale;
        __half h0, m0, h1, m1;
        split2h(v.x, h0, m0); split2h(v.y, h1, m1);
        __half2 ph; ph.x = h0; ph.y = h1;
        __half2 pm; pm.x = m0; pm.y = m1;
        reinterpret_cast<__half2*>(c0)[i] = ph;
        reinterpret_cast<__half2*>(c1)[i] = pm;
    }
}

// fused: per-row L2 norm of features_aug, scaled split2 (x * SA4 / ||row||) -> faug2
__global__ void __launch_bounds__(256)
norm_split2(const float* __restrict__ src,
            __half* __restrict__ c0, __half* __restrict__ c1)
{
    const int row = blockIdx.x;
    const int t = threadIdx.x;
    float4 v = reinterpret_cast<const float4*>(src + (size_t)row * D_BOT)[t];
    float s = v.x * v.x + v.y * v.y + v.z * v.z + v.w * v.w;
    __shared__ float sh[256];
    sh[t] = s;
    __syncthreads();
#pragma unroll
    for (int k = 128; k > 0; k >>= 1) {
        if (t < k) sh[t] += sh[t + k];
        __syncthreads();
    }
    const float inv = SA4 / fmaxf(sqrtf(sh[0]), EPSN);
    v.x *= inv; v.y *= inv; v.z *= inv; v.w *= inv;
    const float x[4] = {v.x, v.y, v.z, v.w};
    const size_t base2 = ((size_t)row * D_BOT + t * 4) >> 1;
#pragma unroll
    for (int p = 0; p < 2; p++) {
        __half h0, m0, h1, m1;
        split2h(x[2 * p], h0, m0);
        split2h(x[2 * p + 1], h1, m1);
        __half2 ph; ph.x = h0; ph.y = h1;
        __half2 pm; pm.x = m0; pm.y = m1;
        reinterpret_cast<__half2*>(c0)[base2 + p] = ph;
        reinterpret_cast<__half2*>(c1)[base2 + p] = pm;
    }
}

// centroid [C,D_BOT] -> cT*SW split2, [D_BOT rows, C_PAD cols]
__global__ void transpose_split2(const float* __restrict__ src)
{
    __shared__ float tile[32][33];
    const int bx = blockIdx.x * 32;  // d
    const int by = blockIdx.y * 32;  // c
    const int x = bx + threadIdx.x;
#pragma unroll
    for (int i = 0; i < 32; i += 8) {
        const int c = by + threadIdx.y + i;
        tile[threadIdx.y + i][threadIdx.x] = (c < C_CLS) ? src[(size_t)c * D_BOT + x] * SW : 0.f;
    }
    __syncthreads();
    const int c2 = by + threadIdx.x;
#pragma unroll
    for (int i = 0; i < 32; i += 8) {
        const int d2 = bx + threadIdx.y + i;
        const float v = tile[threadIdx.x][threadIdx.y + i];
        __half h, m;
        split2h(v, h, m);
        const size_t o = (size_t)d2 * C_PAD + c2;
        g_cTs[0][o] = h;
        g_cTs[1][o] = m;
    }
}

// ===================== masked softmax -> sm1 split2 (col-padded, fp16) ==============
__global__ void __launch_bounds__(256)
mask_softmax(const float* __restrict__ logits)
{
    const int row = blockIdx.x;
    const float* x = logits + (size_t)row * C_CLS;
    const int t = threadIdx.x;

    float v[4];
    float lmax = -INFINITY;
    int limax = C_CLS;
#pragma unroll
    for (int i = 0; i < 4; i++) {
        const int j = t + i * 256;
        const float val = (j < C_CLS) ? x[j] : -INFINITY;
        v[i] = val;
        if (val > lmax) { lmax = val; limax = j; }
    }
    __shared__ float smax[256];
    __shared__ int   simax[256];
    smax[t] = lmax; simax[t] = limax;
    __syncthreads();
#pragma unroll
    for (int s = 128; s > 0; s >>= 1) {
        if (t < s) {
            const float o = smax[t + s]; const int oi = simax[t + s];
            if (o > smax[t] || (o == smax[t] && oi < simax[t])) { smax[t] = o; simax[t] = oi; }
        }
        __syncthreads();
    }
    const int predict = simax[0];
    const float rowmax = smax[0];
    const bool priv = (predict >= SHARE);

    float e[4];
    float lsum = 0.f;
#pragma unroll
    for (int i = 0; i < 4; i++) {
        const int j = t + i * 256;
        float ee = 0.f;
        if (j < C_CLS) {
            bool mask;
            if (j == predict) mask = false;
            else if (priv)    mask = true;
            else              mask = (j < SHARE);
            ee = expf((mask ? NEG_FILL : v[i]) - rowmax);
            lsum += ee;
        }
        e[i] = ee;
    }
    __shared__ float ssum[256];
    ssum[t] = lsum;
    __syncthreads();
#pragma unroll
    for (int s = 128; s > 0; s >>= 1) {
        if (t < s) ssum[t] += ssum[t + s];
        __syncthreads();
    }
    const float inv = 1.f / ssum[0];

    __half* o0 = g_sm1s[0] + (size_t)row * C_PAD;
    __half* o1 = g_sm1s[1] + (size_t)row * C_PAD;
#pragma unroll
    for (int i = 0; i < 4; i++) {
        const int j = t + i * 256;
        const float p = (j < C_CLS) ? e[i] * inv : 0.f;
        __half h, m;
        split2h(p, h, m);
        o0[j] = h;
        o1[j] = m;
    }
}

// ===================== plain row softmax =====================
__global__ void __launch_bounds__(256)
softmax_rows(const float* __restrict__ in, float* __restrict__ outp)
{
    const int row = blockIdx.x;
    const float* x = in + (size_t)row * C_CLS;
    const int t = threadIdx.x;
    float v[4];
    float lmax = -INFINITY;
#pragma unroll
    for (int i = 0; i < 4; i++) {
        const int j = t + i * 256;
        v[i] = (j < C_CLS) ? x[j] : -INFINITY;
        lmax = fmaxf(lmax, v[i]);
    }
    __shared__ float sh[256];
    sh[t] = lmax;
    __syncthreads();
#pragma unroll
    for (int s = 128; s > 0; s >>= 1) {
        if (t < s) sh[t] = fmaxf(sh[t], sh[t + s]);
        __syncthreads();
    }
    const float rowmax = sh[0];
    __syncthreads();
    float e[4];
    float lsum = 0.f;
#pragma unroll
    for (int i = 0; i < 4; i++) {
        const int j = t + i * 256;
        float ee = 0.f;
        if (j < C_CLS) { ee = expf(v[i] - rowmax); lsum += ee; }
        e[i] = ee;
    }
    sh[t] = lsum;
    __syncthreads();
#pragma unroll
    for (int s = 128; s > 0; s >>= 1) {
        if (t < s) sh[t] += sh[t + s];
        __syncthreads();
    }
    const float inv = 1.f / sh[0];
    float* o = outp + (size_t)row * C_CLS;
#pragma unroll
    for (int i = 0; i < 4; i++) {
        const int j = t + i * 256;
        if (j < C_CLS) o[j] = e[i] * inv;
    }
}

// =====================================================================
extern "C" void kernel_launch(void* const* d_in, const int* in_sizes, int n_in,
                              void* d_out, int out_size)
{
    const float* features = (const float*)d_in[0];
    const float* W_b      = (const float*)d_in[1];
    const float* b_b      = (const float*)d_in[2];
    const float* W1       = (const float*)d_in[3];
    const float* W2       = (const float*)d_in[4];
    const float* centroid = (const float*)d_in[5];

    float* out = (float*)d_out;
    float* feats        = out;
    float* features_aug = feats + (size_t)B_ROWS * D_BOT;
    float* outputs1     = features_aug + (size_t)B_ROWS * D_BOT;
    float* outputs2     = outputs1 + (size_t)B_ROWS * C_CLS;
    float* softmax_out  = outputs2 + (size_t)B_ROWS * C_CLS;

    __half *feat2, *Wb2, *feats2, *W1s, *sm1s, *cTs, *faug2, *W2s;
    cudaGetSymbolAddress((void**)&feat2,  g_feat2);
    cudaGetSymbolAddress((void**)&Wb2,    g_Wb2);
    cudaGetSymbolAddress((void**)&feats2, g_feats2);
    cudaGetSymbolAddress((void**)&W1s,    g_W1s);
    cudaGetSymbolAddress((void**)&sm1s,   g_sm1s);
    cudaGetSymbolAddress((void**)&cTs,    g_cTs);
    cudaGetSymbolAddress((void**)&faug2,  g_faug2);
    cudaGetSymbolAddress((void**)&W2s,    g_W2s);

    const size_t S_feat  = (size_t)B_ROWS * D_INF;
    const size_t S_Wb    = (size_t)D_BOT  * D_INF;
    const size_t S_feats = (size_t)B_ROWS * D_BOT;
    const size_t S_W1    = (size_t)C_PAD  * D_BOT;
    const size_t S_sm1   = (size_t)B_ROWS * C_PAD;
    const size_t S_cT    = (size_t)D_BOT  * C_PAD;

    constexpr int TILEB = 128 * 80;
    constexpr int SMEMG = 2 * 4 * TILEB;   // 81920 — 2 CTAs/SM
    cudaFuncSetAttribute(gemm_mma<4, 0>, cudaFuncAttributeMaxDynamicSharedMemorySize, SMEMG);
    cudaFuncSetAttribute(gemm_mma<4, 1>, cudaFuncAttributeMaxDynamicSharedMemorySize, SMEMG);
    cudaFuncSetAttribute(gemm_mma<3, 2>, cudaFuncAttributeMaxDynamicSharedMemorySize, SMEMG);
    cudaFuncSetAttribute(gemm_mma<3, 3>, cudaFuncAttributeMaxDynamicSharedMemorySize, SMEMG);

    const dim3 blk(256);
    const dim3 grid8(8, 64);
    const float invSW = 1.0f / SW;

    // splits for GEMM1
    split2_scale<<<1024, blk>>>(features, B_ROWS, 11, 1.0f, feat2, feat2 + S_feat, B_ROWS);
    split2_scale<<<512,  blk>>>(W_b, D_BOT, 11, SW, Wb2, Wb2 + S_Wb, D_BOT);

    // GEMM1: feats = features @ W_b^T + b_b (epilogue emits feats2 split)
    gemm_mma<4, 0><<<grid8, blk, SMEMG>>>(feat2, S_feat, Wb2, S_Wb, feats, D_INF, D_BOT,
                                          invSW, b_b, feats2, feats2 + S_feats);

    // W1 split
    split2_scale<<<512, blk>>>(W1, C_CLS, 10, SW, W1s, W1s + S_W1, C_PAD);

    // GEMM2: outputs1 = feats @ W1^T
    gemm_mma<4, 1><<<grid8, blk, SMEMG>>>(feats2, S_feats, W1s, S_W1, outputs1, D_BOT, C_CLS,
                                          invSW, nullptr, nullptr, nullptr);

    // centroid^T split + masked softmax
    transpose_split2<<<dim3(D_BOT / 32, C_PAD / 32), dim3(32, 8)>>>(centroid);
    mask_softmax<<<B_ROWS, blk>>>(outputs1);

    // GEMM3: features_aug = sm1 @ centroid + feats
    gemm_mma<3, 2><<<grid8, blk, SMEMG>>>(sm1s, S_sm1, cTs, S_cT, features_aug, C_PAD, D_BOT,
                                          invSW, feats, nullptr, nullptr);

    // fused normalize (+*SA4) + split2
    norm_split2<<<B_ROWS, blk>>>(features_aug, faug2, faug2 + S_feats);
    split2_scale<<<512, blk>>>(W2, C_CLS, 10, SW, W2s, W2s + S_W1, C_PAD);

    // GEMM4: outputs2 = x @ W2^T / TEMP   (escale = 20 / (SW*SA4))
    gemm_mma<3, 3><<<grid8, blk, SMEMG>>>(faug2, S_feats, W2s, S_W1, outputs2, D_BOT, C_CLS,
                                          20.0f / (SW * SA4), nullptr, nullptr, nullptr);

    softmax_rows<<<B_ROWS, blk>>>(outputs2, softmax_out);
}